// round 15
// baseline (speedup 1.0000x reference)
#include <cuda_runtime.h>

// WOS filter: Illinois regula-falsi bracketing (strict >) + exact fused upward walk.
// f(t) = sum_j w_j * [mx_j >= t] (non-increasing). answer = min{mx_e : f(mx_e) <= B},
// else max(mx) (reference clip-to-0 case).
// Bracket tracks F_strict(t) = sum_j w_j * [mx_j > t]:
//   invariant F_strict(lo) > B  and  F_strict(hi) <= B.
// Illinois interpolation uses F magnitudes to converge superlinearly on the
// near-linear staircase; correctness needs ONLY the invariant, not the window.
// Pass 1: cand1 = min{mx > lo} has f(cand1) = F_strict(lo) > B (strict >, holds
//   even if lo equals an element) -> always infeasible, no F needed.
// Pass 2+: fused pass gives cand = min{mx > a} and F = sum w[mx > a] = f(cand)
//   exactly. Hop loop capped at MD (provably sufficient) with warp early-exit.
#define NCH   8
#define MD    54
#define HH    160
#define WW    160
#define HO    158
#define WO    158
#define LPIX  (HO * WO)
#define NPIX  (4 * LPIX)
#define FITER 5

__device__ __forceinline__ float fset_gt(float a, float b) {
    float m;
    asm("set.gt.f32.f32 %0, %1, %2;" : "=f"(m) : "f"(a), "f"(b));
    return m;  // 1.0f if a > b else 0.0f
}

__global__ __launch_bounds__(128, 6) void WOS_72842645340328_kernel(
    const float* __restrict__ x,
    const float* __restrict__ weight,
    const float* __restrict__ bias,
    const float* __restrict__ mask,
    float* __restrict__ out)
{
    const int c = blockIdx.y;                       // warp-uniform channel
    const int n = blockIdx.x * 128 + threadIdx.x;   // pixel task id
    if (n >= NPIX) return;

    int b  = n / LPIX;
    int l  = n - b * LPIX;
    int ho = l / WO;
    int wo = l - ho * WO;

    // Per-channel constants -> uniform registers
    const float* wt = weight + c * MD;
    const float* mk = mask   + c * MD;
    float w[MD];
#pragma unroll
    for (int j = 0; j < MD; ++j) w[j] = wt[j];
    float mkr[MD];
#pragma unroll
    for (int j = 0; j < MD; ++j) mkr[j] = mk[j];
    const float Bc = bias[c];

    // W_tot = sum(w)  (uniform arithmetic)
    float Wt0 = 0.f, Wt1 = 0.f;
#pragma unroll
    for (int j = 0; j < MD; j += 2) { Wt0 += w[j]; Wt1 += w[j + 1]; }
    const float Wtot = Wt0 + Wt1;

    const float* xb = x + ((b * 3) * HH + ho) * WW + wo;

    // Gather + mx build with fused max(|mx|) tracking
    float mx[MD];
    float M0, M1;
    {
        float v0 = __ldg(xb);
        mx[0]  = v0 + mkr[0];
        mx[27] = mkr[27] - v0;
        M0 = fabsf(mx[0]);
        M1 = fabsf(mx[27]);
    }
#pragma unroll
    for (int ch = 0; ch < 3; ++ch)
#pragma unroll
        for (int kh = 0; kh < 3; ++kh)
#pragma unroll
            for (int kw = 0; kw < 3; ++kw) {
                int d = ch * 9 + kh * 3 + kw;
                if (d == 0) continue;
                float v = __ldg(xb + (ch * HH + kh) * WW + kw);
                float p = v + mkr[d];
                float q = mkr[27 + d] - v;
                mx[d]      = p;
                mx[27 + d] = q;
                M0 = fmaxf(M0, fabsf(p));
                M1 = fmaxf(M1, fabsf(q));
            }
    float M  = fmaxf(M0, M1);
    float lo = -M - 0.01f;    // strictly below all elements: F_strict(lo)=Wtot>B
    float hi = M;             // >= all elements: F_strict(hi) = 0 <= B

    // Illinois regula falsi on g(t) = F_strict(t) - B.
    float glo = Wtot - Bc;    // > 0 (B = U(0,1)*Wtot)
    float ghi = -Bc;          // <= 0  (B >= 0)
    int   last = 0;           // +1 = last update was lo side, -1 = hi side
#pragma unroll
    for (int it = 0; it < FITER; ++it) {
        float t = lo + glo * (hi - lo) / (glo - ghi);
        // keep t strictly inside the bracket (fp safety)
        float mid = 0.5f * (lo + hi);
        if (!(t > lo && t < hi)) t = mid;

        float a0 = 0.f, a1 = 0.f, a2 = 0.f, a3 = 0.f;
#pragma unroll
        for (int j = 0; j + 3 < MD; j += 4) {     // j = 0..48, covers 0..51
            a0 = fmaf(fset_gt(mx[j],     t), w[j],     a0);
            a1 = fmaf(fset_gt(mx[j + 1], t), w[j + 1], a1);
            a2 = fmaf(fset_gt(mx[j + 2], t), w[j + 2], a2);
            a3 = fmaf(fset_gt(mx[j + 3], t), w[j + 3], a3);
        }
        a0 = fmaf(fset_gt(mx[52], t), w[52], a0);     // tail 52, 53
        a1 = fmaf(fset_gt(mx[53], t), w[53], a1);
        float g = ((a0 + a1) + (a2 + a3)) - Bc;

        if (g > 0.f) {                 // still infeasible: move lo up
            lo = t; glo = g;
            if (last == 1) ghi *= 0.5f;   // Illinois damping
            last = 1;
        } else {                       // feasible side: move hi down
            hi = t; ghi = g;
            if (last == -1) glo *= 0.5f;
            last = -1;
        }
    }

    const float INF = __int_as_float(0x7f800000);

    // Walk pass 1 (slim): cand1 = min{mx > lo}; exists (F_strict(lo)>B>=0) and is
    // always infeasible (see header).
    float a;
    {
        float c0 = INF, c1 = INF;
#pragma unroll
        for (int j = 0; j < MD; j += 2) {
            if (mx[j]     > lo) c0 = fminf(c0, mx[j]);
            if (mx[j + 1] > lo) c1 = fminf(c1, mx[j + 1]);
        }
        a = fminf(c0, c1);
    }
    float prev = a;
    float ans  = a;
    bool  done = false;

    // Walk passes 2+: fused cand + exact F. Cap = MD hops (provably sufficient).
#pragma unroll 1
    for (int it = 0; it < MD; ++it) {
        if (__all_sync(0xffffffffu, done)) break;
        if (!done) {
            float c0 = INF, c1 = INF;
            float s0 = 0.f, s1 = 0.f, s2 = 0.f, s3 = 0.f;
#pragma unroll
            for (int j = 0; j + 3 < MD; j += 4) {
                bool p0 = mx[j]     > a;
                bool p1 = mx[j + 1] > a;
                bool p2 = mx[j + 2] > a;
                bool p3 = mx[j + 3] > a;
                if (p0) { c0 = fminf(c0, mx[j]);     s0 += w[j];     }
                if (p1) { c1 = fminf(c1, mx[j + 1]); s1 += w[j + 1]; }
                if (p2) { c0 = fminf(c0, mx[j + 2]); s2 += w[j + 2]; }
                if (p3) { c1 = fminf(c1, mx[j + 3]); s3 += w[j + 3]; }
            }
            {   // tail 52, 53
                bool p0 = mx[52] > a;
                bool p1 = mx[53] > a;
                if (p0) { c0 = fminf(c0, mx[52]); s0 += w[52]; }
                if (p1) { c1 = fminf(c1, mx[53]); s1 += w[53]; }
            }
            float cand = fminf(c0, c1);
            float F = (s0 + s1) + (s2 + s3);

            if (cand > 3.0e38f) {        // walked past max element: clip-to-max
                ans = prev; done = true;
            } else if (F <= Bc) {        // F = f(cand) exactly; first feasible wins
                ans = cand; done = true;
            } else {
                ans = cand; prev = cand; a = cand;
            }
        }
    }

    out[n * NCH + c] = ans;
}

extern "C" void kernel_launch(void* const* d_in, const int* in_sizes, int n_in,
                              void* d_out, int out_size)
{
    const float* x      = (const float*)d_in[0];
    const float* weight = (const float*)d_in[1];
    const float* bias   = (const float*)d_in[2];
    const float* mask   = (const float*)d_in[3];
    float* out = (float*)d_out;

    dim3 grid((NPIX + 127) / 128, NCH);
    WOS_72842645340328_kernel<<<grid, 128>>>(x, weight, bias, mask, out);
}

// round 16
// speedup vs baseline: 1.9233x; 1.9233x over previous
#include <cuda_runtime.h>

// WOS filter: R13 algorithm (per-lane abs-bounded strict-> bisection + exact
// fused upward walk), processing TWO pixels per thread for ILP.
// Channel is block-uniform (blockIdx.y) so weights stay in the uniform RF.
// No early returns (walk uses __all_sync): indices clamped, stores predicated.
#define NCH   8
#define MD    54
#define HH    160
#define WW    160
#define HO    158
#define WO    158
#define LPIX  (HO * WO)
#define NPIX  (4 * LPIX)        // 99856
#define HALF  (NPIX / 2)        // 49928
#define BITER 8

__device__ __forceinline__ float fset_gt(float a, float b) {
    float m;
    asm("set.gt.f32.f32 %0, %1, %2;" : "=f"(m) : "f"(a), "f"(b));
    return m;  // 1.0f if a > b else 0.0f
}

__device__ __forceinline__ const float* pix_base(const float* x, int n) {
    int b  = n / LPIX;
    int l  = n - b * LPIX;
    int ho = l / WO;
    int wo = l - ho * WO;
    return x + ((b * 3) * HH + ho) * WW + wo;
}

__global__ __launch_bounds__(128, 3) void WOS_72842645340328_kernel(
    const float* __restrict__ x,
    const float* __restrict__ weight,
    const float* __restrict__ bias,
    const float* __restrict__ mask,
    float* __restrict__ out)
{
    const int c = blockIdx.y;                        // warp-uniform channel
    const int i = blockIdx.x * 128 + threadIdx.x;    // 0 .. 50047
    const int iA = (i < HALF) ? i : (HALF - 1);      // clamp, no early return
    const int nA = iA;
    const int nB = iA + HALF;

    // Per-channel constants -> uniform registers (w persists; mkr is transient)
    const float* wt = weight + c * MD;
    const float* mk = mask   + c * MD;
    float w[MD];
#pragma unroll
    for (int j = 0; j < MD; ++j) w[j] = wt[j];
    const float Bc = bias[c];

    const float* xbA = pix_base(x, nA);
    const float* xbB = pix_base(x, nB);

    // Gather both pixels; fused max(|mx|) per pixel
    float mxA[MD], mxB[MD];
    float MA = 0.f, MB = 0.f;
#pragma unroll
    for (int ch = 0; ch < 3; ++ch)
#pragma unroll
        for (int kh = 0; kh < 3; ++kh)
#pragma unroll
            for (int kw = 0; kw < 3; ++kw) {
                int d = ch * 9 + kh * 3 + kw;
                float m1 = mk[d];
                float m2 = mk[27 + d];
                float vA = __ldg(xbA + (ch * HH + kh) * WW + kw);
                float vB = __ldg(xbB + (ch * HH + kh) * WW + kw);
                float pA = vA + m1, qA = m2 - vA;
                float pB = vB + m1, qB = m2 - vB;
                mxA[d] = pA; mxA[27 + d] = qA;
                mxB[d] = pB; mxB[27 + d] = qB;
                MA = fmaxf(MA, fabsf(pA)); MA = fmaxf(MA, fabsf(qA));
                MB = fmaxf(MB, fabsf(pB)); MB = fmaxf(MB, fabsf(qB));
            }
    float loA = -MA - 0.01f, hiA = MA;
    float loB = -MB - 0.01f, hiB = MB;

    // Dual bisection with STRICT > (invariant F_strict(lo) > B).
    // Rolled loop: two independent chains give the ILP; keeps I$ small.
#pragma unroll 1
    for (int it = 0; it < BITER; ++it) {
        float midA = 0.5f * (loA + hiA);
        float midB = 0.5f * (loB + hiB);
        float a0 = 0.f, a1 = 0.f, a2 = 0.f, a3 = 0.f;
        float b0 = 0.f, b1 = 0.f, b2 = 0.f, b3 = 0.f;
#pragma unroll
        for (int j = 0; j + 3 < MD; j += 4) {
            a0 = fmaf(fset_gt(mxA[j],     midA), w[j],     a0);
            a1 = fmaf(fset_gt(mxA[j + 1], midA), w[j + 1], a1);
            a2 = fmaf(fset_gt(mxA[j + 2], midA), w[j + 2], a2);
            a3 = fmaf(fset_gt(mxA[j + 3], midA), w[j + 3], a3);
            b0 = fmaf(fset_gt(mxB[j],     midB), w[j],     b0);
            b1 = fmaf(fset_gt(mxB[j + 1], midB), w[j + 1], b1);
            b2 = fmaf(fset_gt(mxB[j + 2], midB), w[j + 2], b2);
            b3 = fmaf(fset_gt(mxB[j + 3], midB), w[j + 3], b3);
        }
        a0 = fmaf(fset_gt(mxA[52], midA), w[52], a0);
        a1 = fmaf(fset_gt(mxA[53], midA), w[53], a1);
        b0 = fmaf(fset_gt(mxB[52], midB), w[52], b0);
        b1 = fmaf(fset_gt(mxB[53], midB), w[53], b1);
        float FA = (a0 + a1) + (a2 + a3);
        float FB = (b0 + b1) + (b2 + b3);
        if (FA <= Bc) hiA = midA; else loA = midA;
        if (FB <= Bc) hiB = midB; else loB = midB;
    }

    const float INF = __int_as_float(0x7f800000);

    // Walk pass 1 (slim): cand1 = min{mx > lo}; always exists & infeasible
    // (strict > makes this hold even if lo equals an element).
    float aA, aB;
    {
        float c0 = INF, c1 = INF, d0 = INF, d1 = INF;
#pragma unroll
        for (int j = 0; j < MD; j += 2) {
            if (mxA[j]     > loA) c0 = fminf(c0, mxA[j]);
            if (mxA[j + 1] > loA) c1 = fminf(c1, mxA[j + 1]);
            if (mxB[j]     > loB) d0 = fminf(d0, mxB[j]);
            if (mxB[j + 1] > loB) d1 = fminf(d1, mxB[j + 1]);
        }
        aA = fminf(c0, c1);
        aB = fminf(d0, d1);
    }
    float prevA = aA, ansA = aA; bool doneA = false;
    float prevB = aB, ansB = aB; bool doneB = false;

    // Walk passes 2+: fused cand + exact F for each pixel. Cap MD (provable).
#pragma unroll 1
    for (int it = 0; it < MD; ++it) {
        if (__all_sync(0xffffffffu, doneA && doneB)) break;
        if (!doneA) {
            float c0 = INF, c1 = INF;
            float s0 = 0.f, s1 = 0.f, s2 = 0.f, s3 = 0.f;
#pragma unroll
            for (int j = 0; j + 3 < MD; j += 4) {
                bool p0 = mxA[j]     > aA;
                bool p1 = mxA[j + 1] > aA;
                bool p2 = mxA[j + 2] > aA;
                bool p3 = mxA[j + 3] > aA;
                if (p0) { c0 = fminf(c0, mxA[j]);     s0 += w[j];     }
                if (p1) { c1 = fminf(c1, mxA[j + 1]); s1 += w[j + 1]; }
                if (p2) { c0 = fminf(c0, mxA[j + 2]); s2 += w[j + 2]; }
                if (p3) { c1 = fminf(c1, mxA[j + 3]); s3 += w[j + 3]; }
            }
            {
                bool p0 = mxA[52] > aA;
                bool p1 = mxA[53] > aA;
                if (p0) { c0 = fminf(c0, mxA[52]); s0 += w[52]; }
                if (p1) { c1 = fminf(c1, mxA[53]); s1 += w[53]; }
            }
            float cand = fminf(c0, c1);
            float F = (s0 + s1) + (s2 + s3);
            if (cand > 3.0e38f)      { ansA = prevA; doneA = true; }
            else if (F <= Bc)        { ansA = cand;  doneA = true; }
            else { ansA = cand; prevA = cand; aA = cand; }
        }
        if (!doneB) {
            float c0 = INF, c1 = INF;
            float s0 = 0.f, s1 = 0.f, s2 = 0.f, s3 = 0.f;
#pragma unroll
            for (int j = 0; j + 3 < MD; j += 4) {
                bool p0 = mxB[j]     > aB;
                bool p1 = mxB[j + 1] > aB;
                bool p2 = mxB[j + 2] > aB;
                bool p3 = mxB[j + 3] > aB;
                if (p0) { c0 = fminf(c0, mxB[j]);     s0 += w[j];     }
                if (p1) { c1 = fminf(c1, mxB[j + 1]); s1 += w[j + 1]; }
                if (p2) { c0 = fminf(c0, mxB[j + 2]); s2 += w[j + 2]; }
                if (p3) { c1 = fminf(c1, mxB[j + 3]); s3 += w[j + 3]; }
            }
            {
                bool p0 = mxB[52] > aB;
                bool p1 = mxB[53] > aB;
                if (p0) { c0 = fminf(c0, mxB[52]); s0 += w[52]; }
                if (p1) { c1 = fminf(c1, mxB[53]); s1 += w[53]; }
            }
            float cand = fminf(c0, c1);
            float F = (s0 + s1) + (s2 + s3);
            if (cand > 3.0e38f)      { ansB = prevB; doneB = true; }
            else if (F <= Bc)        { ansB = cand;  doneB = true; }
            else { ansB = cand; prevB = cand; aB = cand; }
        }
    }

    if (i < HALF) {
        out[nA * NCH + c] = ansA;
        out[nB * NCH + c] = ansB;
    }
}

extern "C" void kernel_launch(void* const* d_in, const int* in_sizes, int n_in,
                              void* d_out, int out_size)
{
    const float* x      = (const float*)d_in[0];
    const float* weight = (const float*)d_in[1];
    const float* bias   = (const float*)d_in[2];
    const float* mask   = (const float*)d_in[3];
    float* out = (float*)d_out;

    dim3 grid((HALF + 127) / 128, NCH);   // 391 x 8
    WOS_72842645340328_kernel<<<grid, 128>>>(x, weight, bias, mask, out);
}

// round 17
// speedup vs baseline: 2.1789x; 1.1329x over previous
#include <cuda_runtime.h>

// WOS filter: R13 algorithm with a branchless common-path walk.
// f(t) = sum_j w_j * [mx_j >= t]. answer = min{mx_e : f(mx_e) <= B}, else max(mx).
// Bisection tracks F_strict(t) = sum w[mx > t]; invariant F_strict(lo) > B.
// Pass 1 (slim): cand1 = min{mx > lo}, always exists & infeasible (strict >).
// Then TWO unconditional fused walk iterations (no branches; FSEL state updates),
// then a guarded loop for rare stragglers (cap MD, provably sufficient).
#define NCH   8
#define MD    54
#define HH    160
#define WW    160
#define HO    158
#define WO    158
#define LPIX  (HO * WO)
#define NPIX  (4 * LPIX)
#define BITER 8

__device__ __forceinline__ float fset_gt(float a, float b) {
    float m;
    asm("set.gt.f32.f32 %0, %1, %2;" : "=f"(m) : "f"(a), "f"(b));
    return m;  // 1.0f if a > b else 0.0f
}

__global__ __launch_bounds__(128, 6) void WOS_72842645340328_kernel(
    const float* __restrict__ x,
    const float* __restrict__ weight,
    const float* __restrict__ bias,
    const float* __restrict__ mask,
    float* __restrict__ out)
{
    const int c = blockIdx.y;                       // warp-uniform channel
    const int n = blockIdx.x * 128 + threadIdx.x;   // pixel task id
    if (n >= NPIX) return;

    int b  = n / LPIX;
    int l  = n - b * LPIX;
    int ho = l / WO;
    int wo = l - ho * WO;

    // Per-channel constants -> uniform registers
    const float* wt = weight + c * MD;
    const float* mk = mask   + c * MD;
    float w[MD];
#pragma unroll
    for (int j = 0; j < MD; ++j) w[j] = wt[j];
    float mkr[MD];
#pragma unroll
    for (int j = 0; j < MD; ++j) mkr[j] = mk[j];
    const float Bc = bias[c];

    const float* xb = x + ((b * 3) * HH + ho) * WW + wo;

    // Gather + mx build with fused max(|mx|) tracking
    float mx[MD];
    float M0, M1;
    {
        float v0 = __ldg(xb);
        mx[0]  = v0 + mkr[0];
        mx[27] = mkr[27] - v0;
        M0 = fabsf(mx[0]);
        M1 = fabsf(mx[27]);
    }
#pragma unroll
    for (int ch = 0; ch < 3; ++ch)
#pragma unroll
        for (int kh = 0; kh < 3; ++kh)
#pragma unroll
            for (int kw = 0; kw < 3; ++kw) {
                int d = ch * 9 + kh * 3 + kw;
                if (d == 0) continue;
                float v = __ldg(xb + (ch * HH + kh) * WW + kw);
                float p = v + mkr[d];
                float q = mkr[27 + d] - v;
                mx[d]      = p;
                mx[27 + d] = q;
                M0 = fmaxf(M0, fabsf(p));
                M1 = fmaxf(M1, fabsf(q));
            }
    float M  = fmaxf(M0, M1);
    float lo = -M - 0.01f;    // strictly below all elements: F_strict(lo)=sum(w)>B
    float hi = M;             // >= all elements: F_strict(hi) = 0 <= B

    // Bisection with STRICT > (invariant F_strict(lo) > B holds even when a
    // midpoint coincides exactly with an element).
#pragma unroll
    for (int it = 0; it < BITER; ++it) {
        float mid = 0.5f * (lo + hi);
        float a0 = 0.f, a1 = 0.f, a2 = 0.f, a3 = 0.f;
#pragma unroll
        for (int j = 0; j + 3 < MD; j += 4) {     // j = 0..48, covers 0..51
            a0 = fmaf(fset_gt(mx[j],     mid), w[j],     a0);
            a1 = fmaf(fset_gt(mx[j + 1], mid), w[j + 1], a1);
            a2 = fmaf(fset_gt(mx[j + 2], mid), w[j + 2], a2);
            a3 = fmaf(fset_gt(mx[j + 3], mid), w[j + 3], a3);
        }
        a0 = fmaf(fset_gt(mx[52], mid), w[52], a0);   // tail 52, 53
        a1 = fmaf(fset_gt(mx[53], mid), w[53], a1);
        float F = (a0 + a1) + (a2 + a3);
        if (F <= Bc) hi = mid; else lo = mid;
    }

    const float INF = __int_as_float(0x7f800000);

    // Walk pass 1 (slim): cand1 = min{mx > lo}; exists (F_strict(lo)>B>=0) and
    // is always infeasible: f(cand1) = sum w[mx >= cand1] = F_strict(lo) > B.
    float a;
    {
        float c0 = INF, c1 = INF;
#pragma unroll
        for (int j = 0; j < MD; j += 2) {
            if (mx[j]     > lo) c0 = fminf(c0, mx[j]);
            if (mx[j + 1] > lo) c1 = fminf(c1, mx[j + 1]);
        }
        a = fminf(c0, c1);
    }
    float prev = a;
    float ans  = a;
    bool  done = false;

    // --- Two unconditional, branchless fused walk iterations ---
    // (warp-max hops is >= 2 fused iterations for nearly all warps; running
    //  them straight-line removes BSSY/BSYNC/BRA/VOTE from the common path)
#pragma unroll
    for (int u = 0; u < 2; ++u) {
        float c0 = INF, c1 = INF;
        float s0 = 0.f, s1 = 0.f, s2 = 0.f, s3 = 0.f;
#pragma unroll
        for (int j = 0; j + 3 < MD; j += 4) {
            bool p0 = mx[j]     > a;
            bool p1 = mx[j + 1] > a;
            bool p2 = mx[j + 2] > a;
            bool p3 = mx[j + 3] > a;
            if (p0) { c0 = fminf(c0, mx[j]);     s0 += w[j];     }
            if (p1) { c1 = fminf(c1, mx[j + 1]); s1 += w[j + 1]; }
            if (p2) { c0 = fminf(c0, mx[j + 2]); s2 += w[j + 2]; }
            if (p3) { c1 = fminf(c1, mx[j + 3]); s3 += w[j + 3]; }
        }
        {   // tail 52, 53
            bool p0 = mx[52] > a;
            bool p1 = mx[53] > a;
            if (p0) { c0 = fminf(c0, mx[52]); s0 += w[52]; }
            if (p1) { c1 = fminf(c1, mx[53]); s1 += w[53]; }
        }
        float cand = fminf(c0, c1);
        float F = (s0 + s1) + (s2 + s3);

        bool infinite = cand > 3.0e38f;
        bool feas     = F <= Bc;
        float sel = infinite ? prev : cand;   // result if we stop/advance this iter
        ans  = done ? ans  : sel;
        prev = done ? prev : sel;
        a    = done ? a    : sel;             // if infinite, a is dead anyway
        done = done || infinite || feas;
    }

    // --- Rare stragglers: guarded loop (cap MD, provably sufficient) ---
#pragma unroll 1
    for (int it = 0; it < MD; ++it) {
        if (__all_sync(0xffffffffu, done)) break;
        if (!done) {
            float c0 = INF, c1 = INF;
            float s0 = 0.f, s1 = 0.f, s2 = 0.f, s3 = 0.f;
#pragma unroll
            for (int j = 0; j + 3 < MD; j += 4) {
                bool p0 = mx[j]     > a;
                bool p1 = mx[j + 1] > a;
                bool p2 = mx[j + 2] > a;
                bool p3 = mx[j + 3] > a;
                if (p0) { c0 = fminf(c0, mx[j]);     s0 += w[j];     }
                if (p1) { c1 = fminf(c1, mx[j + 1]); s1 += w[j + 1]; }
                if (p2) { c0 = fminf(c0, mx[j + 2]); s2 += w[j + 2]; }
                if (p3) { c1 = fminf(c1, mx[j + 3]); s3 += w[j + 3]; }
            }
            {   // tail 52, 53
                bool p0 = mx[52] > a;
                bool p1 = mx[53] > a;
                if (p0) { c0 = fminf(c0, mx[52]); s0 += w[52]; }
                if (p1) { c1 = fminf(c1, mx[53]); s1 += w[53]; }
            }
            float cand = fminf(c0, c1);
            float F = (s0 + s1) + (s2 + s3);

            if (cand > 3.0e38f)      { ans = prev; done = true; }
            else if (F <= Bc)        { ans = cand; done = true; }
            else { ans = cand; prev = cand; a = cand; }
        }
    }

    out[n * NCH + c] = ans;
}

extern "C" void kernel_launch(void* const* d_in, const int* in_sizes, int n_in,
                              void* d_out, int out_size)
{
    const float* x      = (const float*)d_in[0];
    const float* weight = (const float*)d_in[1];
    const float* bias   = (const float*)d_in[2];
    const float* mask   = (const float*)d_in[3];
    float* out = (float*)d_out;

    dim3 grid((NPIX + 127) / 128, NCH);
    WOS_72842645340328_kernel<<<grid, 128>>>(x, weight, bias, mask, out);
}